// round 3
// baseline (speedup 1.0000x reference)
#include <cuda_runtime.h>
#include <mma.h>
#include <cstdint>

using namespace nvcuda;

// ---------------- problem constants ----------------
#define HW     4096      // 64*64
#define IMGW   64
#define BATCH  16
#define CIN    256
#define C3     768       // qkv channels
#define CCAT   512       // attention output channels
#define COUT   256
#define NHEAD  64
#define ATT_EPS 1e-5f

// ---------------- scratch (device globals; no allocations) ----------------
__device__ float g_qkv [(size_t)BATCH * C3   * HW];
__device__ float g_agg [(size_t)BATCH * C3   * HW];
__device__ float g_attn[(size_t)BATCH * CCAT * HW];
__device__ float g_vk  [BATCH * NHEAD * 72];

// ==========================================================================
// 3xTF32 tensor-core GEMM + BN + ReLU (1x1 conv), fp32-accurate.
//   Out[b, m, n] = relu( scale[m] * sum_k W[m,k] * X[b,k,n] + bias[m] )
// Block tile 128(M) x 128(N), BK=32, 256 threads = 8 warps.
// Each warp: 64x32 tile via 4x2 wmma m16n16k8 fragments.
// Per operand: hi = tf32(x), lo = tf32(x - hi); acc += hi*hi + hi*lo + lo*hi.
// ==========================================================================
#define LDA 40    // 32 + 8 pad
#define LDB 136   // 128 + 8 pad
#define LDC 132   // 128 + 4 pad

template<int Mt, int Kt, bool PROJ>
__global__ __launch_bounds__(256)
void gemm_tc3_bn_relu(const float* __restrict__ Xext,
                      const float* __restrict__ Wm,
                      const float* __restrict__ scale,
                      const float* __restrict__ bias,
                      float* __restrict__ OutExt)
{
    __shared__ __align__(16) float smem[128 * LDA + 32 * LDB];
    float* As = smem;             // [128][LDA]
    float* Bs = smem + 128 * LDA; // [32][LDB]
    float* Cs = smem;             // reused post-k-loop: [64][LDC]

    const float* __restrict__ X   = PROJ ? g_attn : Xext;
    float*       __restrict__ Out = PROJ ? OutExt : g_qkv;

    const int b     = blockIdx.z;
    const int mBase = blockIdx.y * 128;
    const int nBase = blockIdx.x * 128;
    const int tid   = threadIdx.x;
    const int wid   = tid >> 5;
    const int warpM = wid & 1;    // 0..1
    const int warpN = wid >> 1;   // 0..3

    const float* __restrict__ Xb = X + (size_t)b * Kt * HW;

    wmma::fragment<wmma::accumulator, 16, 16, 8, float> acc[4][2];
    #pragma unroll
    for (int i = 0; i < 4; i++)
        #pragma unroll
        for (int j = 0; j < 2; j++) wmma::fill_fragment(acc[i][j], 0.f);

    for (int k0 = 0; k0 < Kt; k0 += 32) {
        #pragma unroll
        for (int t = 0; t < 4; t++) {
            int idx = tid + t * 256;
            int r = idx >> 3, c4 = (idx & 7) * 4;
            float4 v = *reinterpret_cast<const float4*>(
                &Wm[(size_t)(mBase + r) * Kt + k0 + c4]);
            *reinterpret_cast<float4*>(&As[r * LDA + c4]) = v;
        }
        #pragma unroll
        for (int t = 0; t < 4; t++) {
            int idx = tid + t * 256;
            int r = idx >> 5, c4 = (idx & 31) * 4;
            float4 v = *reinterpret_cast<const float4*>(
                &Xb[(size_t)(k0 + r) * HW + nBase + c4]);
            *reinterpret_cast<float4*>(&Bs[r * LDB + c4]) = v;
        }
        __syncthreads();

        #pragma unroll
        for (int kk = 0; kk < 4; kk++) {
            wmma::fragment<wmma::matrix_a, 16, 16, 8, wmma::precision::tf32,
                           wmma::row_major> ahi[4], alo[4];
            wmma::fragment<wmma::matrix_b, 16, 16, 8, wmma::precision::tf32,
                           wmma::row_major> bhi[2], blo[2];
            #pragma unroll
            for (int i = 0; i < 4; i++) {
                wmma::load_matrix_sync(
                    ahi[i], &As[(warpM * 64 + i * 16) * LDA + kk * 8], LDA);
                #pragma unroll
                for (int t = 0; t < ahi[i].num_elements; t++) {
                    float a  = ahi[i].x[t];
                    float hi = wmma::__float_to_tf32(a);
                    ahi[i].x[t] = hi;
                    alo[i].x[t] = wmma::__float_to_tf32(a - hi);
                }
            }
            #pragma unroll
            for (int j = 0; j < 2; j++) {
                wmma::load_matrix_sync(
                    bhi[j], &Bs[(kk * 8) * LDB + warpN * 32 + j * 16], LDB);
                #pragma unroll
                for (int t = 0; t < bhi[j].num_elements; t++) {
                    float v  = bhi[j].x[t];
                    float hi = wmma::__float_to_tf32(v);
                    bhi[j].x[t] = hi;
                    blo[j].x[t] = wmma::__float_to_tf32(v - hi);
                }
            }
            // small terms first, then the dominant hi*hi
            #pragma unroll
            for (int i = 0; i < 4; i++)
                #pragma unroll
                for (int j = 0; j < 2; j++) {
                    wmma::mma_sync(acc[i][j], alo[i], bhi[j], acc[i][j]);
                    wmma::mma_sync(acc[i][j], ahi[i], blo[j], acc[i][j]);
                    wmma::mma_sync(acc[i][j], ahi[i], bhi[j], acc[i][j]);
                }
        }
        __syncthreads();
    }

    // epilogue: two 64-row passes via smem staging, fused BN + ReLU
    #pragma unroll
    for (int p = 0; p < 2; p++) {
        if (warpM == p) {
            #pragma unroll
            for (int i = 0; i < 4; i++)
                #pragma unroll
                for (int j = 0; j < 2; j++)
                    wmma::store_matrix_sync(
                        &Cs[(i * 16) * LDC + warpN * 32 + j * 16],
                        acc[i][j], LDC, wmma::mem_row_major);
        }
        __syncthreads();
        #pragma unroll
        for (int t = 0; t < 8; t++) {
            int idx = tid + t * 256;
            int r = idx >> 5, c4 = (idx & 31) * 4;
            int m = mBase + p * 64 + r;
            const float sc = scale[m], bi = bias[m];
            float4 v = *reinterpret_cast<const float4*>(&Cs[r * LDC + c4]);
            v.x = fmaxf(fmaf(v.x, sc, bi), 0.f);
            v.y = fmaxf(fmaf(v.y, sc, bi), 0.f);
            v.z = fmaxf(fmaf(v.z, sc, bi), 0.f);
            v.w = fmaxf(fmaf(v.w, sc, bi), 0.f);
            *reinterpret_cast<float4*>(
                &Out[(size_t)b * Mt * HW + (size_t)m * HW + nBase + c4]) = v;
        }
        __syncthreads();
    }
}

// ==========================================================================
// Fused depthwise 5x5 (pad 2, +bias) then per-channel 1x1 (*w, +bias).
// ==========================================================================
__global__ __launch_bounds__(256)
void dw5x5_pw_kernel(const float* __restrict__ dw_w,
                     const float* __restrict__ dw_b,
                     const float* __restrict__ pw_w,
                     const float* __restrict__ pw_b)
{
    const int c = blockIdx.y;
    const int b = blockIdx.z;
    const int p = blockIdx.x * 256 + threadIdx.x;
    const int y = p >> 6;
    const int x = p & 63;

    const float* __restrict__ src = g_qkv + ((size_t)b * C3 + c) * HW;

    float wreg[25];
    #pragma unroll
    for (int i = 0; i < 25; i++) wreg[i] = __ldg(&dw_w[c * 25 + i]);

    float s = 0.f;
    #pragma unroll
    for (int dy = 0; dy < 5; dy++) {
        const int yy = y + dy - 2;
        if (yy < 0 || yy >= IMGW) continue;
        const float* row = src + yy * IMGW;
        #pragma unroll
        for (int dx = 0; dx < 5; dx++) {
            const int xx = x + dx - 2;
            if (xx < 0 || xx >= IMGW) continue;
            s = fmaf(__ldg(&row[xx]), wreg[dy * 5 + dx], s);
        }
    }
    s = fmaf(s + __ldg(&dw_b[c]), __ldg(&pw_w[c]), __ldg(&pw_b[c]));
    g_agg[((size_t)b * C3 + c) * HW + p] = s;
}

// ==========================================================================
// Attention phase 1: per (b, head): vk[d][e] = sum_n v*relu(k); ksum[e]
// ==========================================================================
__global__ __launch_bounds__(256)
void attn_reduce_kernel()
{
    const int head = blockIdx.x;
    const int b    = blockIdx.y;
    const float* __restrict__ src = (head < 32) ? g_qkv : g_agg;
    const int ch0 = (head & 31) * 24;
    const float* __restrict__ base = src + ((size_t)b * C3 + ch0) * HW;

    float acc[72];
    #pragma unroll
    for (int i = 0; i < 72; i++) acc[i] = 0.f;

    for (int n = threadIdx.x; n < HW; n += 256) {
        float kv[8], vv[8];
        #pragma unroll
        for (int e = 0; e < 8; e++) kv[e] = fmaxf(base[(size_t)(8 + e) * HW + n], 0.f);
        #pragma unroll
        for (int d = 0; d < 8; d++) vv[d] = base[(size_t)(16 + d) * HW + n];
        #pragma unroll
        for (int d = 0; d < 8; d++)
            #pragma unroll
            for (int e = 0; e < 8; e++)
                acc[d * 8 + e] = fmaf(vv[d], kv[e], acc[d * 8 + e]);
        #pragma unroll
        for (int e = 0; e < 8; e++) acc[64 + e] += kv[e];
    }

    __shared__ float s_acc[72];
    if (threadIdx.x < 72) s_acc[threadIdx.x] = 0.f;
    __syncthreads();

    const int lane = threadIdx.x & 31;
    #pragma unroll
    for (int i = 0; i < 72; i++) {
        float v = acc[i];
        #pragma unroll
        for (int off = 16; off > 0; off >>= 1)
            v += __shfl_down_sync(0xffffffffu, v, off);
        if (lane == 0) atomicAdd(&s_acc[i], v);
    }
    __syncthreads();
    if (threadIdx.x < 72)
        g_vk[((size_t)b * NHEAD + head) * 72 + threadIdx.x] = s_acc[threadIdx.x];
}

// ==========================================================================
// Attention phase 2: apply + normalize
// ==========================================================================
__global__ __launch_bounds__(256)
void attn_apply_kernel()
{
    const int head = blockIdx.y;
    const int b    = blockIdx.z;
    const int n    = blockIdx.x * 256 + threadIdx.x;

    __shared__ float s[72];
    if (threadIdx.x < 72)
        s[threadIdx.x] = g_vk[((size_t)b * NHEAD + head) * 72 + threadIdx.x];
    __syncthreads();

    const float* __restrict__ src = (head < 32) ? g_qkv : g_agg;
    const int ch0 = (head & 31) * 24;
    const float* __restrict__ base = src + ((size_t)b * C3 + ch0) * HW;

    float q[8];
    #pragma unroll
    for (int e = 0; e < 8; e++) q[e] = fmaxf(base[(size_t)e * HW + n], 0.f);

    float denom = ATT_EPS;
    #pragma unroll
    for (int e = 0; e < 8; e++) denom = fmaf(s[64 + e], q[e], denom);
    const float inv = 1.f / denom;

    float* obase = g_attn + ((size_t)b * CCAT + head * 8) * HW + n;
    #pragma unroll
    for (int d = 0; d < 8; d++) {
        float o = 0.f;
        #pragma unroll
        for (int e = 0; e < 8; e++) o = fmaf(s[d * 8 + e], q[e], o);
        obase[(size_t)d * HW] = o * inv;
    }
}

// ==========================================================================
// launcher
// ==========================================================================
extern "C" void kernel_launch(void* const* d_in, const int* in_sizes, int n_in,
                              void* d_out, int out_size)
{
    const float* x            = (const float*)d_in[0];
    const float* qkv_w        = (const float*)d_in[1];
    const float* qkv_bn_scale = (const float*)d_in[2];
    const float* qkv_bn_bias  = (const float*)d_in[3];
    const float* agg_dw_w     = (const float*)d_in[4];
    const float* agg_dw_b     = (const float*)d_in[5];
    const float* agg_pw_w     = (const float*)d_in[6];
    const float* agg_pw_b     = (const float*)d_in[7];
    const float* proj_w       = (const float*)d_in[8];
    const float* proj_bn_scale= (const float*)d_in[9];
    const float* proj_bn_bias = (const float*)d_in[10];
    float* out = (float*)d_out;

    {
        dim3 grid(HW / 128, C3 / 128, BATCH);
        gemm_tc3_bn_relu<C3, CIN, false><<<grid, 256>>>(
            x, qkv_w, qkv_bn_scale, qkv_bn_bias, nullptr);
    }
    {
        dim3 grid(HW / 256, C3, BATCH);
        dw5x5_pw_kernel<<<grid, 256>>>(agg_dw_w, agg_dw_b, agg_pw_w, agg_pw_b);
    }
    {
        dim3 grid(NHEAD, BATCH);
        attn_reduce_kernel<<<grid, 256>>>();
    }
    {
        dim3 grid(HW / 256, NHEAD, BATCH);
        attn_apply_kernel<<<grid, 256>>>();
    }
    {
        dim3 grid(HW / 128, COUT / 128, BATCH);
        gemm_tc3_bn_relu<COUT, CCAT, true><<<grid, 256>>>(
            nullptr, proj_w, proj_bn_scale, proj_bn_bias, out);
    }
}

// round 5
// speedup vs baseline: 1.7170x; 1.7170x over previous
#include <cuda_runtime.h>
#include <cuda_bf16.h>
#include <mma.h>
#include <cstdint>

using namespace nvcuda;

// ---------------- problem constants ----------------
#define HW     4096      // 64*64
#define IMGW   64
#define BATCH  16
#define CIN    256
#define C3     768
#define CCAT   512
#define COUT   256
#define NHEAD  64
#define ATT_EPS 1e-5f

// ---------------- scratch (device globals; no allocations) ----------------
__device__ float g_qkv [(size_t)BATCH * C3   * HW];
__device__ float g_agg [(size_t)BATCH * C3   * HW];
__device__ float g_attn[(size_t)BATCH * CCAT * HW];
__device__ float g_vk  [BATCH * NHEAD * 72];

// ==========================================================================
// bf16x3 (error-compensated) wmma GEMM + BN + ReLU (1x1 conv).
//   Out[b,m,n] = relu(scale[m] * sum_k W[m,k] X[b,k,n] + bias[m])
// Block tile 128(M) x 128(N), BK=32, 256 threads = 8 warps.
// Warp tile 64x32 via 4x2 wmma m16n16k16 bf16 fragments, 2 k-steps per BK.
// Per element: hi = bf16(x), lo = bf16(x - hi); acc += Ahi*Bhi + Ahi*Blo + Alo*Bhi.
// hi/lo conversion done once during SMEM staging (bf16 tiles), not per fragment.
// ==========================================================================
#define LDA 40    // 32 + 8 pad (bf16)
#define LDB 136   // 128 + 8 pad (bf16)
#define LDC 132   // 128 + 4 pad (fp32, epilogue reuse)

// smem layout (bytes): Ahi[128*40*2]=10240, Alo=10240, Bhi[32*136*2]=8704, Blo=8704
#define OFF_AHI 0
#define OFF_ALO 10240
#define OFF_BHI 20480
#define OFF_BLO 29184
#define SMEM_BYTES 37888   // >= 64*132*4 = 33792 for epilogue reuse

template<int Mt, int Kt, bool PROJ>
__global__ __launch_bounds__(256)
void gemm_bf16x3_bn_relu(const float* __restrict__ Xext,
                         const float* __restrict__ Wm,
                         const float* __restrict__ scale,
                         const float* __restrict__ bias,
                         float* __restrict__ OutExt)
{
    __shared__ __align__(16) char smem[SMEM_BYTES];
    __nv_bfloat16* Ahi = reinterpret_cast<__nv_bfloat16*>(smem + OFF_AHI);
    __nv_bfloat16* Alo = reinterpret_cast<__nv_bfloat16*>(smem + OFF_ALO);
    __nv_bfloat16* Bhi = reinterpret_cast<__nv_bfloat16*>(smem + OFF_BHI);
    __nv_bfloat16* Blo = reinterpret_cast<__nv_bfloat16*>(smem + OFF_BLO);
    float* Cs = reinterpret_cast<float*>(smem);   // epilogue staging [64][LDC]

    const float* __restrict__ X   = PROJ ? g_attn : Xext;
    float*       __restrict__ Out = PROJ ? OutExt : g_qkv;

    const int b     = blockIdx.z;
    const int mBase = blockIdx.y * 128;
    const int nBase = blockIdx.x * 128;
    const int tid   = threadIdx.x;
    const int wid   = tid >> 5;
    const int warpM = wid & 1;    // 0..1 (64 rows each)
    const int warpN = wid >> 1;   // 0..3 (32 cols each)

    const float* __restrict__ Xb = X + (size_t)b * Kt * HW;

    wmma::fragment<wmma::accumulator, 16, 16, 16, float> acc[4][2];
    #pragma unroll
    for (int i = 0; i < 4; i++)
        #pragma unroll
        for (int j = 0; j < 2; j++) wmma::fill_fragment(acc[i][j], 0.f);

    for (int k0 = 0; k0 < Kt; k0 += 32) {
        // ---- stage A: W[mBase..+128][k0..+32] -> bf16 hi/lo [m][k]
        #pragma unroll
        for (int t = 0; t < 4; t++) {
            int idx = tid + t * 256;
            int r = idx >> 3, c4 = (idx & 7) * 4;
            float4 v = *reinterpret_cast<const float4*>(
                &Wm[(size_t)(mBase + r) * Kt + k0 + c4]);
            float xs[4] = {v.x, v.y, v.z, v.w};
            union { __nv_bfloat16 h[4]; uint2 u; } ph, pl;
            #pragma unroll
            for (int j = 0; j < 4; j++) {
                __nv_bfloat16 hh = __float2bfloat16_rn(xs[j]);
                ph.h[j] = hh;
                pl.h[j] = __float2bfloat16_rn(xs[j] - __bfloat162float(hh));
            }
            *reinterpret_cast<uint2*>(&Ahi[r * LDA + c4]) = ph.u;
            *reinterpret_cast<uint2*>(&Alo[r * LDA + c4]) = pl.u;
        }
        // ---- stage B: X[k0..+32][nBase..+128] -> bf16 hi/lo [k][n]
        #pragma unroll
        for (int t = 0; t < 4; t++) {
            int idx = tid + t * 256;
            int r = idx >> 5, c4 = (idx & 31) * 4;
            float4 v = *reinterpret_cast<const float4*>(
                &Xb[(size_t)(k0 + r) * HW + nBase + c4]);
            float xs[4] = {v.x, v.y, v.z, v.w};
            union { __nv_bfloat16 h[4]; uint2 u; } ph, pl;
            #pragma unroll
            for (int j = 0; j < 4; j++) {
                __nv_bfloat16 hh = __float2bfloat16_rn(xs[j]);
                ph.h[j] = hh;
                pl.h[j] = __float2bfloat16_rn(xs[j] - __bfloat162float(hh));
            }
            *reinterpret_cast<uint2*>(&Bhi[r * LDB + c4]) = ph.u;
            *reinterpret_cast<uint2*>(&Blo[r * LDB + c4]) = pl.u;
        }
        __syncthreads();

        #pragma unroll
        for (int kk = 0; kk < 2; kk++) {   // 2 x K16 steps
            wmma::fragment<wmma::matrix_a, 16, 16, 16, __nv_bfloat16,
                           wmma::row_major> afh[4], afl[4];
            wmma::fragment<wmma::matrix_b, 16, 16, 16, __nv_bfloat16,
                           wmma::row_major> bfh[2], bfl[2];
            #pragma unroll
            for (int i = 0; i < 4; i++) {
                const int ro = (warpM * 64 + i * 16) * LDA + kk * 16;
                wmma::load_matrix_sync(afh[i], &Ahi[ro], LDA);
                wmma::load_matrix_sync(afl[i], &Alo[ro], LDA);
            }
            #pragma unroll
            for (int j = 0; j < 2; j++) {
                const int ro = (kk * 16) * LDB + warpN * 32 + j * 16;
                wmma::load_matrix_sync(bfh[j], &Bhi[ro], LDB);
                wmma::load_matrix_sync(bfl[j], &Blo[ro], LDB);
            }
            #pragma unroll
            for (int i = 0; i < 4; i++)
                #pragma unroll
                for (int j = 0; j < 2; j++) {
                    wmma::mma_sync(acc[i][j], afl[i], bfh[j], acc[i][j]);
                    wmma::mma_sync(acc[i][j], afh[i], bfl[j], acc[i][j]);
                    wmma::mma_sync(acc[i][j], afh[i], bfh[j], acc[i][j]);
                }
        }
        __syncthreads();
    }

    // ---- epilogue: two 64-row passes via smem staging, fused BN + ReLU
    #pragma unroll
    for (int p = 0; p < 2; p++) {
        if (warpM == p) {
            #pragma unroll
            for (int i = 0; i < 4; i++)
                #pragma unroll
                for (int j = 0; j < 2; j++)
                    wmma::store_matrix_sync(
                        &Cs[(i * 16) * LDC + warpN * 32 + j * 16],
                        acc[i][j], LDC, wmma::mem_row_major);
        }
        __syncthreads();
        #pragma unroll
        for (int t = 0; t < 8; t++) {
            int idx = tid + t * 256;
            int r = idx >> 5, c4 = (idx & 31) * 4;
            int m = mBase + p * 64 + r;
            const float sc = scale[m], bi = bias[m];
            float4 v = *reinterpret_cast<const float4*>(&Cs[r * LDC + c4]);
            v.x = fmaxf(fmaf(v.x, sc, bi), 0.f);
            v.y = fmaxf(fmaf(v.y, sc, bi), 0.f);
            v.z = fmaxf(fmaf(v.z, sc, bi), 0.f);
            v.w = fmaxf(fmaf(v.w, sc, bi), 0.f);
            *reinterpret_cast<float4*>(
                &Out[(size_t)b * Mt * HW + (size_t)m * HW + nBase + c4]) = v;
        }
        __syncthreads();
    }
}

// ==========================================================================
// Fused depthwise 5x5 (pad 2, +bias) then per-channel 1x1 (*w, +bias).
// ==========================================================================
__global__ __launch_bounds__(256)
void dw5x5_pw_kernel(const float* __restrict__ dw_w,
                     const float* __restrict__ dw_b,
                     const float* __restrict__ pw_w,
                     const float* __restrict__ pw_b)
{
    const int c = blockIdx.y;
    const int b = blockIdx.z;
    const int p = blockIdx.x * 256 + threadIdx.x;
    const int y = p >> 6;
    const int x = p & 63;

    const float* __restrict__ src = g_qkv + ((size_t)b * C3 + c) * HW;

    float wreg[25];
    #pragma unroll
    for (int i = 0; i < 25; i++) wreg[i] = __ldg(&dw_w[c * 25 + i]);

    float s = 0.f;
    #pragma unroll
    for (int dy = 0; dy < 5; dy++) {
        const int yy = y + dy - 2;
        if (yy < 0 || yy >= IMGW) continue;
        const float* row = src + yy * IMGW;
        #pragma unroll
        for (int dx = 0; dx < 5; dx++) {
            const int xx = x + dx - 2;
            if (xx < 0 || xx >= IMGW) continue;
            s = fmaf(__ldg(&row[xx]), wreg[dy * 5 + dx], s);
        }
    }
    s = fmaf(s + __ldg(&dw_b[c]), __ldg(&pw_w[c]), __ldg(&pw_b[c]));
    g_agg[((size_t)b * C3 + c) * HW + p] = s;
}

// ==========================================================================
// Attention phase 1: per (b, head): vk[d][e] = sum_n v*relu(k); ksum[e]
// ==========================================================================
__global__ __launch_bounds__(256)
void attn_reduce_kernel()
{
    const int head = blockIdx.x;
    const int b    = blockIdx.y;
    const float* __restrict__ src = (head < 32) ? g_qkv : g_agg;
    const int ch0 = (head & 31) * 24;
    const float* __restrict__ base = src + ((size_t)b * C3 + ch0) * HW;

    float acc[72];
    #pragma unroll
    for (int i = 0; i < 72; i++) acc[i] = 0.f;

    for (int n = threadIdx.x; n < HW; n += 256) {
        float kv[8], vv[8];
        #pragma unroll
        for (int e = 0; e < 8; e++) kv[e] = fmaxf(base[(size_t)(8 + e) * HW + n], 0.f);
        #pragma unroll
        for (int d = 0; d < 8; d++) vv[d] = base[(size_t)(16 + d) * HW + n];
        #pragma unroll
        for (int d = 0; d < 8; d++)
            #pragma unroll
            for (int e = 0; e < 8; e++)
                acc[d * 8 + e] = fmaf(vv[d], kv[e], acc[d * 8 + e]);
        #pragma unroll
        for (int e = 0; e < 8; e++) acc[64 + e] += kv[e];
    }

    __shared__ float s_acc[72];
    if (threadIdx.x < 72) s_acc[threadIdx.x] = 0.f;
    __syncthreads();

    const int lane = threadIdx.x & 31;
    #pragma unroll
    for (int i = 0; i < 72; i++) {
        float v = acc[i];
        #pragma unroll
        for (int off = 16; off > 0; off >>= 1)
            v += __shfl_down_sync(0xffffffffu, v, off);
        if (lane == 0) atomicAdd(&s_acc[i], v);
    }
    __syncthreads();
    if (threadIdx.x < 72)
        g_vk[((size_t)b * NHEAD + head) * 72 + threadIdx.x] = s_acc[threadIdx.x];
}

// ==========================================================================
// Attention phase 2: apply + normalize
// ==========================================================================
__global__ __launch_bounds__(256)
void attn_apply_kernel()
{
    const int head = blockIdx.y;
    const int b    = blockIdx.z;
    const int n    = blockIdx.x * 256 + threadIdx.x;

    __shared__ float s[72];
    if (threadIdx.x < 72)
        s[threadIdx.x] = g_vk[((size_t)b * NHEAD + head) * 72 + threadIdx.x];
    __syncthreads();

    const float* __restrict__ src = (head < 32) ? g_qkv : g_agg;
    const int ch0 = (head & 31) * 24;
    const float* __restrict__ base = src + ((size_t)b * C3 + ch0) * HW;

    float q[8];
    #pragma unroll
    for (int e = 0; e < 8; e++) q[e] = fmaxf(base[(size_t)e * HW + n], 0.f);

    float denom = ATT_EPS;
    #pragma unroll
    for (int e = 0; e < 8; e++) denom = fmaf(s[64 + e], q[e], denom);
    const float inv = 1.f / denom;

    float* obase = g_attn + ((size_t)b * CCAT + head * 8) * HW + n;
    #pragma unroll
    for (int d = 0; d < 8; d++) {
        float o = 0.f;
        #pragma unroll
        for (int e = 0; e < 8; e++) o = fmaf(s[d * 8 + e], q[e], o);
        obase[(size_t)d * HW] = o * inv;
    }
}

// ==========================================================================
// launcher
// ==========================================================================
extern "C" void kernel_launch(void* const* d_in, const int* in_sizes, int n_in,
                              void* d_out, int out_size)
{
    const float* x            = (const float*)d_in[0];
    const float* qkv_w        = (const float*)d_in[1];
    const float* qkv_bn_scale = (const float*)d_in[2];
    const float* qkv_bn_bias  = (const float*)d_in[3];
    const float* agg_dw_w     = (const float*)d_in[4];
    const float* agg_dw_b     = (const float*)d_in[5];
    const float* agg_pw_w     = (const float*)d_in[6];
    const float* agg_pw_b     = (const float*)d_in[7];
    const float* proj_w       = (const float*)d_in[8];
    const float* proj_bn_scale= (const float*)d_in[9];
    const float* proj_bn_bias = (const float*)d_in[10];
    float* out = (float*)d_out;

    // 1) qkv = relu(bn(conv1x1(x)))  [bf16x3 tensor cores]
    {
        dim3 grid(HW / 128, C3 / 128, BATCH);
        gemm_bf16x3_bn_relu<C3, CIN, false><<<grid, 256>>>(
            x, qkv_w, qkv_bn_scale, qkv_bn_bias, nullptr);
    }
    // 2) agg = pw(dw5x5(qkv))
    {
        dim3 grid(HW / 256, C3, BATCH);
        dw5x5_pw_kernel<<<grid, 256>>>(agg_dw_w, agg_dw_b, agg_pw_w, agg_pw_b);
    }
    // 3a) per-head vk / ksum
    {
        dim3 grid(NHEAD, BATCH);
        attn_reduce_kernel<<<grid, 256>>>();
    }
    // 3b) apply + normalize
    {
        dim3 grid(HW / 256, NHEAD, BATCH);
        attn_apply_kernel<<<grid, 256>>>();
    }
    // 4) out = relu(bn(conv1x1(g_attn)))  [bf16x3 tensor cores]
    {
        dim3 grid(HW / 128, COUT / 128, BATCH);
        gemm_bf16x3_bn_relu<COUT, CCAT, true><<<grid, 256>>>(
            nullptr, proj_w, proj_bn_scale, proj_bn_bias, out);
    }
}